// round 3
// baseline (speedup 1.0000x reference)
#include <cuda_runtime.h>
#include <cstdint>

#define NN 50000
#define NE 800000
#define FIN 8          // concat(x[6], pos[2])
#define HID 64
#define NOUT 10
#define NK 4           // K+1 weight slices

// ---------------- scratch (no allocation allowed) ----------------
struct Scratch {
    alignas(128) float deg[NN];
    alignas(128) float dinv[NN];
    alignas(128) int   cnt[NN];
    alignas(128) int   rowptr[NN + 1];
    alignas(128) int   cursor[NN];
    alignas(128) int   col[NE];
    alignas(128) float val[NE];
    alignas(128) float h0 [NN * FIN];
    alignas(128) float t8a[NN * FIN];
    alignas(128) float t8b[NN * FIN];
    alignas(128) float t8c[NN * FIN];
    alignas(128) float hA[NN * HID];
    alignas(128) float hB[NN * HID];
    alignas(128) float hC[NN * HID];
    alignas(128) float hD[NN * HID];
};
__device__ Scratch g_s;
__device__ int g_is64;   // 1 if edge_index is int64, 0 if int32

// ---------------- edge_index dtype detection ----------------
// For int64 (little-endian) every odd 32-bit word is a high word == 0
// (indices are in [0, 50000)). For int32 odd words are random node ids.
__global__ void k_detect(const int* __restrict__ ei32) {
    if (blockIdx.x == 0 && threadIdx.x == 0) g_is64 = 1;   // will be ANDed away
    __threadfence();
    int t = blockIdx.x * blockDim.x + threadIdx.x;          // 1024 threads
    const int step = NE / 1024;
    long long idx = 2LL * (long long)t * step + 1;          // odd position
    if (idx < 2LL * NE && ei32[idx] != 0) atomicAnd(&g_is64, 0);
}

__device__ __forceinline__ int load_src(const int* ei32, int e, int is64) {
    int v = is64 ? ei32[2 * e] : ei32[e];
    return min(max(v, 0), NN - 1);
}
__device__ __forceinline__ int load_dst(const int* ei32, int e, int is64) {
    long long base = is64 ? 2LL * ((long long)NE + e) : (long long)NE + e;
    int v = ei32[base];
    return min(max(v, 0), NN - 1);
}

// ---------------- graph preprocessing ----------------
__global__ void k_zero(float* __restrict__ deg, int* __restrict__ cnt) {
    int i = blockIdx.x * blockDim.x + threadIdx.x;
    if (i < NN) { deg[i] = 0.0f; cnt[i] = 0; }
}

__global__ void k_deg_cnt(const int* __restrict__ ei32,
                          const float* __restrict__ ea,
                          float* __restrict__ deg, int* __restrict__ cnt) {
    int e = blockIdx.x * blockDim.x + threadIdx.x;
    if (e >= NE) return;
    int is64 = g_is64;
    int d = load_dst(ei32, e, is64);
    atomicAdd(&deg[d], ea[e]);
    atomicAdd(&cnt[d], 1);
}

__global__ void k_dinv(const float* __restrict__ deg, float* __restrict__ dinv) {
    int i = blockIdx.x * blockDim.x + threadIdx.x;
    if (i >= NN) return;
    float d = deg[i];
    dinv[i] = (d > 0.0f) ? rsqrtf(d) : 0.0f;
}

// single-block exclusive scan of cnt -> rowptr (+ cursor copy)
__global__ void k_scan(const int* __restrict__ cnt,
                       int* __restrict__ rowptr, int* __restrict__ cursor) {
    const int T = 1024;
    const int per = (NN + T - 1) / T;
    int tid = threadIdx.x;
    int lane = tid & 31, wid = tid >> 5;
    int base = tid * per;

    int s = 0;
    for (int i = 0; i < per; i++) {
        int j = base + i;
        if (j < NN) s += cnt[j];
    }
    int v = s;
    #pragma unroll
    for (int o = 1; o < 32; o <<= 1) {
        int n = __shfl_up_sync(0xFFFFFFFFu, v, o);
        if (lane >= o) v += n;
    }
    __shared__ int wsum[32];
    if (lane == 31) wsum[wid] = v;
    __syncthreads();
    if (wid == 0) {
        int w = wsum[lane];
        #pragma unroll
        for (int o = 1; o < 32; o <<= 1) {
            int n = __shfl_up_sync(0xFFFFFFFFu, w, o);
            if (lane >= o) w += n;
        }
        wsum[lane] = w;
    }
    __syncthreads();
    int excl = v - s + (wid > 0 ? wsum[wid - 1] : 0);

    int off = excl;
    for (int i = 0; i < per; i++) {
        int j = base + i;
        if (j < NN) {
            rowptr[j] = off;
            cursor[j] = off;
            off += cnt[j];
        }
    }
    if (tid == 0) rowptr[NN] = NE;
}

__global__ void k_fill(const int* __restrict__ ei32,
                       const float* __restrict__ ea,
                       const float* __restrict__ dinv,
                       int* __restrict__ cursor,
                       int* __restrict__ col, float* __restrict__ val) {
    int e = blockIdx.x * blockDim.x + threadIdx.x;
    if (e >= NE) return;
    int is64 = g_is64;
    int srcv = load_src(ei32, e, is64);
    int dstv = load_dst(ei32, e, is64);
    float nv = dinv[srcv] * ea[e] * dinv[dstv];
    int p = atomicAdd(&cursor[dstv], 1);
    col[p] = srcv;
    val[p] = nv;
}

__global__ void k_concat(const float* __restrict__ x, const float* __restrict__ pos,
                         float* __restrict__ h0) {
    int i = blockIdx.x * blockDim.x + threadIdx.x;
    if (i >= NN) return;
    float* o = h0 + i * FIN;
    const float* xi = x + i * 6;
    o[0] = xi[0]; o[1] = xi[1]; o[2] = xi[2];
    o[3] = xi[3]; o[4] = xi[4]; o[5] = xi[5];
    o[6] = pos[i * 2 + 0];
    o[7] = pos[i * 2 + 1];
}

// ---------------- propagate (CSR gather, pull) ----------------
__global__ void k_prop8(const float* __restrict__ h, float* __restrict__ o,
                        const int* __restrict__ rowptr,
                        const int* __restrict__ col, const float* __restrict__ val) {
    int node = blockIdx.x * blockDim.x + threadIdx.x;
    if (node >= NN) return;
    int b = rowptr[node], e = rowptr[node + 1];
    float4 a0 = {0, 0, 0, 0}, a1 = {0, 0, 0, 0};
    for (int i = b; i < e; i++) {
        int s = col[i];
        float v = val[i];
        const float4* hp = (const float4*)(h + s * FIN);
        float4 x0 = hp[0], x1 = hp[1];
        a0.x += v * x0.x; a0.y += v * x0.y; a0.z += v * x0.z; a0.w += v * x0.w;
        a1.x += v * x1.x; a1.y += v * x1.y; a1.z += v * x1.z; a1.w += v * x1.w;
    }
    float4* op = (float4*)(o + node * FIN);
    op[0] = a0; op[1] = a1;
}

// warp per node; lane f covers features {f, f+32}
__global__ void k_prop64(const float* __restrict__ h, float* __restrict__ o,
                         const int* __restrict__ rowptr,
                         const int* __restrict__ col, const float* __restrict__ val) {
    int node = blockIdx.x * (blockDim.x >> 5) + (threadIdx.x >> 5);
    int lane = threadIdx.x & 31;
    if (node >= NN) return;
    int b = rowptr[node], e = rowptr[node + 1];
    float a0 = 0.0f, a1 = 0.0f;
    #pragma unroll 2
    for (int i = b; i < e; i++) {
        int s = col[i];
        float v = val[i];
        const float* hp = h + s * HID;
        a0 += v * hp[lane];
        a1 += v * hp[32 + lane];
    }
    o[node * HID + lane] = a0;
    o[node * HID + 32 + lane] = a1;
}

// ---------------- fused layer GEMMs: out = sum_k h_k @ W[k] + b ----------------
__global__ void k_gemm_l1(const float* __restrict__ h0, const float* __restrict__ h1,
                          const float* __restrict__ h2, const float* __restrict__ h3,
                          const float* __restrict__ W, const float* __restrict__ bias,
                          float* __restrict__ outp) {
    __shared__ float sW[NK * FIN * HID];   // 8KB
    __shared__ float sb[HID];
    for (int i = threadIdx.x; i < NK * FIN * HID; i += blockDim.x) sW[i] = W[i];
    if (threadIdx.x < HID) sb[threadIdx.x] = bias[threadIdx.x];
    __syncthreads();

    int row = blockIdx.x * blockDim.x + threadIdx.x;
    if (row >= NN) return;
    const float* hs[NK] = {h0 + row * FIN, h1 + row * FIN, h2 + row * FIN, h3 + row * FIN};

    float acc[HID];
    #pragma unroll
    for (int c = 0; c < HID; c++) acc[c] = sb[c];

    for (int kk = 0; kk < NK; kk++) {
        const float4* hp = (const float4*)hs[kk];
        const float* Wk = sW + kk * FIN * HID;
        float4 h04 = hp[0], h14 = hp[1];
        float hv[FIN] = {h04.x, h04.y, h04.z, h04.w, h14.x, h14.y, h14.z, h14.w};
        #pragma unroll
        for (int k = 0; k < FIN; k++) {
            const float* w = Wk + k * HID;
            #pragma unroll
            for (int c = 0; c < HID; c++) acc[c] += hv[k] * w[c];
        }
    }
    float* op = outp + row * HID;
    #pragma unroll
    for (int c = 0; c < HID; c++) op[c] = fmaxf(acc[c], 0.0f);
}

__global__ void k_gemm_l2(const float* __restrict__ h0, const float* __restrict__ h1,
                          const float* __restrict__ h2, const float* __restrict__ h3,
                          const float* __restrict__ W, const float* __restrict__ bias,
                          float* __restrict__ outp) {
    extern __shared__ float sW[];          // 4*64*64*4 = 64KB
    __shared__ float sb[HID];
    for (int i = threadIdx.x; i < NK * HID * HID; i += blockDim.x) sW[i] = W[i];
    if (threadIdx.x < HID) sb[threadIdx.x] = bias[threadIdx.x];
    __syncthreads();

    int row = blockIdx.x * blockDim.x + threadIdx.x;
    if (row >= NN) return;
    const float* hs[NK] = {h0 + row * HID, h1 + row * HID, h2 + row * HID, h3 + row * HID};

    float acc[HID];
    #pragma unroll
    for (int c = 0; c < HID; c++) acc[c] = sb[c];

    for (int kk = 0; kk < NK; kk++) {
        const float4* hp = (const float4*)hs[kk];
        const float* Wk = sW + kk * HID * HID;
        for (int k4 = 0; k4 < HID / 4; k4++) {
            float4 hv = hp[k4];
            const float* w = Wk + (k4 * 4) * HID;
            #pragma unroll
            for (int c = 0; c < HID; c++) acc[c] += hv.x * w[c];
            #pragma unroll
            for (int c = 0; c < HID; c++) acc[c] += hv.y * w[HID + c];
            #pragma unroll
            for (int c = 0; c < HID; c++) acc[c] += hv.z * w[2 * HID + c];
            #pragma unroll
            for (int c = 0; c < HID; c++) acc[c] += hv.w * w[3 * HID + c];
        }
    }
    float* op = outp + row * HID;   // may alias h0 (in-place safe: per-row private)
    #pragma unroll
    for (int c = 0; c < HID; c++) op[c] = fmaxf(acc[c], 0.0f);
}

// layer-3 GEMM with fused log-softmax epilogue
__global__ void k_gemm_l3(const float* __restrict__ h0, const float* __restrict__ h1,
                          const float* __restrict__ h2, const float* __restrict__ h3,
                          const float* __restrict__ W, const float* __restrict__ bias,
                          float* __restrict__ outp) {
    __shared__ float sW[NK * HID * NOUT];  // 10KB
    __shared__ float sb[NOUT];
    for (int i = threadIdx.x; i < NK * HID * NOUT; i += blockDim.x) sW[i] = W[i];
    if (threadIdx.x < NOUT) sb[threadIdx.x] = bias[threadIdx.x];
    __syncthreads();

    int row = blockIdx.x * blockDim.x + threadIdx.x;
    if (row >= NN) return;
    const float* hs[NK] = {h0 + row * HID, h1 + row * HID, h2 + row * HID, h3 + row * HID};

    float acc[NOUT];
    #pragma unroll
    for (int c = 0; c < NOUT; c++) acc[c] = sb[c];

    for (int kk = 0; kk < NK; kk++) {
        const float4* hp = (const float4*)hs[kk];
        const float* Wk = sW + kk * HID * NOUT;
        for (int k4 = 0; k4 < HID / 4; k4++) {
            float4 hv = hp[k4];
            const float* w = Wk + (k4 * 4) * NOUT;
            #pragma unroll
            for (int c = 0; c < NOUT; c++) acc[c] += hv.x * w[c];
            #pragma unroll
            for (int c = 0; c < NOUT; c++) acc[c] += hv.y * w[NOUT + c];
            #pragma unroll
            for (int c = 0; c < NOUT; c++) acc[c] += hv.z * w[2 * NOUT + c];
            #pragma unroll
            for (int c = 0; c < NOUT; c++) acc[c] += hv.w * w[3 * NOUT + c];
        }
    }
    // log_softmax
    float m = acc[0];
    #pragma unroll
    for (int c = 1; c < NOUT; c++) m = fmaxf(m, acc[c]);
    float s = 0.0f;
    #pragma unroll
    for (int c = 0; c < NOUT; c++) s += expf(acc[c] - m);
    float l = m + logf(s);
    float* op = outp + row * NOUT;
    #pragma unroll
    for (int c = 0; c < NOUT; c++) op[c] = acc[c] - l;
}

// ---------------- launch ----------------
extern "C" void kernel_launch(void* const* d_in, const int* in_sizes, int n_in,
                              void* d_out, int out_size) {
    // Identify inputs by element count (robust to metadata ordering).
    const float *x = 0, *pos = 0, *ea = 0, *W1 = 0, *b1 = 0, *W2 = 0, *b2 = 0,
                *W3 = 0, *b3 = 0;
    const int* ei32 = 0;
    for (int i = 0; i < n_in; i++) {
        switch (in_sizes[i]) {
            case 1600000: ei32 = (const int*)d_in[i]; break;   // dtype detected on device
            case  800000: ea  = (const float*)d_in[i]; break;
            case  300000: x   = (const float*)d_in[i]; break;
            case  100000: pos = (const float*)d_in[i]; break;
            case    2048: W1  = (const float*)d_in[i]; break;
            case   16384: W2  = (const float*)d_in[i]; break;
            case    2560: W3  = (const float*)d_in[i]; break;
            case      10: b3  = (const float*)d_in[i]; break;
            case      64:
                if (!b1) b1 = (const float*)d_in[i];
                else     b2 = (const float*)d_in[i];
                break;
            default: break;
        }
    }
    float* out = (float*)d_out;

    Scratch* S;
    cudaGetSymbolAddress((void**)&S, g_s);
    cudaFuncSetAttribute(k_gemm_l2, cudaFuncAttributeMaxDynamicSharedMemorySize,
                         NK * HID * HID * (int)sizeof(float));

    const int BE = (NE + 255) / 256;
    const int BN = (NN + 255) / 256;
    const int BG = (NN + 127) / 128;
    const int BW = (NN + 7) / 8;          // prop64: 8 warps/block

    k_detect<<<4, 256>>>(ei32);
    k_zero<<<BN, 256>>>(S->deg, S->cnt);
    k_deg_cnt<<<BE, 256>>>(ei32, ea, S->deg, S->cnt);
    k_dinv<<<BN, 256>>>(S->deg, S->dinv);
    k_scan<<<1, 1024>>>(S->cnt, S->rowptr, S->cursor);
    k_fill<<<BE, 256>>>(ei32, ea, S->dinv, S->cursor, S->col, S->val);
    k_concat<<<BN, 256>>>(x, pos, S->h0);

    // layer 1 (F=8 -> 64)
    k_prop8<<<BN, 256>>>(S->h0,  S->t8a, S->rowptr, S->col, S->val);
    k_prop8<<<BN, 256>>>(S->t8a, S->t8b, S->rowptr, S->col, S->val);
    k_prop8<<<BN, 256>>>(S->t8b, S->t8c, S->rowptr, S->col, S->val);
    k_gemm_l1<<<BG, 128>>>(S->h0, S->t8a, S->t8b, S->t8c, W1, b1, S->hA);

    // layer 2 (64 -> 64), in-place output into hA
    k_prop64<<<BW, 256>>>(S->hA, S->hB, S->rowptr, S->col, S->val);
    k_prop64<<<BW, 256>>>(S->hB, S->hC, S->rowptr, S->col, S->val);
    k_prop64<<<BW, 256>>>(S->hC, S->hD, S->rowptr, S->col, S->val);
    k_gemm_l2<<<BG, 128, NK * HID * HID * (int)sizeof(float)>>>(
        S->hA, S->hB, S->hC, S->hD, W2, b2, S->hA);

    // layer 3 (64 -> 10) + log_softmax
    k_prop64<<<BW, 256>>>(S->hA, S->hB, S->rowptr, S->col, S->val);
    k_prop64<<<BW, 256>>>(S->hB, S->hC, S->rowptr, S->col, S->val);
    k_prop64<<<BW, 256>>>(S->hC, S->hD, S->rowptr, S->col, S->val);
    k_gemm_l3<<<BG, 128>>>(S->hA, S->hB, S->hC, S->hD, W3, b3, out);
}